// round 4
// baseline (speedup 1.0000x reference)
#include <cuda_runtime.h>
#include <cuda_bf16.h>
#include <cstdint>

#define FIN   64
#define FOUT  64
#define FH    128
#define LATD  512
#define NB    16
#define HW    16384
#define KTOT  53760
#define WS    106496   // bf16 elements of packed weights per sample

// per-sample bf16 element offsets of fragment-ordered weight buffers
#define WIN_HI   0        // O=128 I=64  (8192 ele), lo at +8192
#define WMIDA_HI 16384    // O=128 I=128 (16384),   lo at +16384
#define WMIDB_HI 49152
#define WOUT_HI  81920    // O=64 I=128  (8192),    lo at +8192
#define WSH_HI   98304    // O=64 I=64   (4096),    lo at +4096

__device__ __align__(16) __nv_bfloat16 g_wb[NB * WS];
__device__ __align__(16) float g_bias[NB * 512];

// ---------------- helpers ----------------
__device__ __forceinline__ unsigned long long pack2(float a, float b) {
    unsigned long long r;
    asm("mov.b64 %0, {%1,%2};" : "=l"(r) : "r"(__float_as_uint(a)), "r"(__float_as_uint(b)));
    return r;
}
__device__ __forceinline__ void unpack2(unsigned long long v, float& a, float& b) {
    unsigned u0, u1;
    asm("mov.b64 {%0,%1}, %2;" : "=r"(u0), "=r"(u1) : "l"(v));
    a = __uint_as_float(u0); b = __uint_as_float(u1);
}
__device__ __forceinline__ void ffma2(unsigned long long& d, unsigned long long a, unsigned long long b) {
    asm("fma.rn.f32x2 %0, %1, %2, %0;" : "+l"(d) : "l"(a), "l"(b));
}
__device__ __forceinline__ void split2(float f0, float f1, uint32_t& hi, uint32_t& lo) {
    // hi = bf16x2(low=f0, high=f1); lo = bf16x2 of residuals
    asm("cvt.rn.bf16x2.f32 %0, %1, %2;" : "=r"(hi) : "f"(f1), "f"(f0));
    float h0 = __uint_as_float(hi << 16);
    float h1 = __uint_as_float(hi & 0xFFFF0000u);
    float r0 = f0 - h0, r1 = f1 - h1;
    asm("cvt.rn.bf16x2.f32 %0, %1, %2;" : "=r"(lo) : "f"(r1), "f"(r0));
}

__device__ __forceinline__ void mma16816(float d[4],
    const uint32_t a[4], uint32_t b0, uint32_t b1)
{
    asm volatile(
        "mma.sync.aligned.m16n8k16.row.col.f32.bf16.bf16.f32 "
        "{%0,%1,%2,%3}, {%4,%5,%6,%7}, {%8,%9}, {%0,%1,%2,%3};"
        : "+f"(d[0]), "+f"(d[1]), "+f"(d[2]), "+f"(d[3])
        : "r"(a[0]), "r"(a[1]), "r"(a[2]), "r"(a[3]), "r"(b0), "r"(b1));
}

// ============================================================
// Kernel A: hypernetwork GEMM, f32x2 sample-pair packed,
// + bf16 hi/lo pack into mma.sync B-fragment order.
// ============================================================
__global__ __launch_bounds__(256) void hyper_kernel(
    const float* __restrict__ lat,
    const float* __restrict__ Wm,
    const float* __restrict__ bias)
{
    __shared__ unsigned long long slat2[8][LATD];   // 32 KB: (sample 2j, 2j+1)
    for (int idx = threadIdx.x; idx < 8 * LATD; idx += 256) {
        int j = idx >> 9, l = idx & 511;
        slat2[j][l] = pack2(lat[(2 * j) * LATD + l], lat[(2 * j + 1) * LATD + l]);
    }
    __syncthreads();

    int k = blockIdx.x * 256 + threadIdx.x;   // 210*256 == 53760 exact

    unsigned long long acc2[8];
#pragma unroll
    for (int j = 0; j < 8; j++) acc2[j] = 0ull;

    const float4* wr = (const float4*)(Wm + (size_t)k * LATD);
#pragma unroll 4
    for (int l4 = 0; l4 < LATD / 4; l4++) {
        float4 w = wr[l4];
        float wv[4] = {w.x, w.y, w.z, w.w};
        int l = l4 * 4;
#pragma unroll
        for (int i = 0; i < 4; i++) {
            unsigned long long ad = pack2(wv[i], wv[i]);
#pragma unroll
            for (int j = 0; j < 8; j++) ffma2(acc2[j], ad, slat2[j][l + i]);
        }
    }

    const float RS128 = 0.08838834764831845f;  // 1/sqrt(128)
    const float RS64  = 0.125f;                // 1/sqrt(64)
    float bk = bias[k];

    // map k -> (layer, o, i) -> fragment element index
    bool isBias = false;
    float scale = 1.f;
    int o = 0, i = 0, I = 0, baseHi = 0, loDelta = 0;
    if (k < 8192) {
        o = k >> 6; i = k & 63; I = 64;
        baseHi = WIN_HI; loDelta = 8192; scale = RS128;
    } else if (k < 24576) {
        int idx = k - 8192; o = idx >> 7; i = idx & 127; I = 128;
        baseHi = WMIDA_HI; loDelta = 16384; scale = RS128;
    } else if (k < 40960) {
        int idx = k - 24576; o = idx >> 7; i = idx & 127; I = 128;
        baseHi = WMIDB_HI; loDelta = 16384; scale = RS128;
    } else if (k < 49152) {
        int idx = k - 40960; o = idx >> 7; i = idx & 127; I = 128;
        baseHi = WOUT_HI; loDelta = 8192; scale = RS64;
    } else if (k < 53248) {
        int idx = k - 49152; o = idx >> 6; i = idx & 63; I = 64;
        baseHi = WSH_HI; loDelta = 4096; scale = RS64;
    } else {
        isBias = true;
    }

    int fel = 0;
    if (!isBias) {
        int KT = I / 16;
        int nt = o >> 3, kt = i >> 4;
        int tl = (o & 7) * 4 + ((i & 7) >> 1);          // lane
        int el = (((i >> 3) & 1) << 1) | (i & 1);       // elem within 4-group
        fel = baseHi + ((nt * KT + kt) * 32 + tl) * 4 + el;
    }

#pragma unroll
    for (int j = 0; j < 8; j++) {
        float v0, v1;
        unpack2(acc2[j], v0, v1);
        float vs[2] = {v0, v1};
#pragma unroll
        for (int s2 = 0; s2 < 2; s2++) {
            int s = 2 * j + s2;
            if (isBias) {
                g_bias[s * 512 + (k - 53248)] = vs[s2] + bk;
            } else {
                float v = (vs[s2] + bk) * scale;
                __nv_bfloat16 h = __float2bfloat16(v);
                __nv_bfloat16 l = __float2bfloat16(v - __bfloat162float(h));
                g_wb[(size_t)s * WS + fel]           = h;
                g_wb[(size_t)s * WS + fel + loDelta] = l;
            }
        }
    }
}

// ============================================================
// Kernel B: mma.sync fused block; activations register-resident.
// kt-outer / nt-chunked-inner ordering: same-accumulator reuse
// distance = 8 MMAs, so HMMA latency is covered by ILP.
// ============================================================
template <int KT, int NT, bool ZERO>
__device__ __forceinline__ void layer_mma(
    float (*D)[4],
    const uint32_t (*Ahi)[4], const uint32_t (*Alo)[4],
    const char* __restrict__ sm, int hiOffB, int loOffB, int lane)
{
    if (ZERO) {
#pragma unroll
        for (int nt = 0; nt < NT; nt++) {
            D[nt][0] = 0.f; D[nt][1] = 0.f; D[nt][2] = 0.f; D[nt][3] = 0.f;
        }
    }
#pragma unroll
    for (int kt = 0; kt < KT; kt++) {
#pragma unroll
        for (int nc = 0; nc < NT; nc += 8) {
            uint2 bh[8], bl[8];
#pragma unroll
            for (int j = 0; j < 8; j++) {
                int fo = (((nc + j) * KT + kt) * 32 + lane) * 8;
                bh[j] = *(const uint2*)(sm + hiOffB + fo);
                bl[j] = *(const uint2*)(sm + loOffB + fo);
            }
#pragma unroll
            for (int j = 0; j < 8; j++) mma16816(D[nc + j], Ahi[kt], bh[j].x, bh[j].y);
#pragma unroll
            for (int j = 0; j < 8; j++) mma16816(D[nc + j], Alo[kt], bh[j].x, bh[j].y);
#pragma unroll
            for (int j = 0; j < 8; j++) mma16816(D[nc + j], Ahi[kt], bl[j].x, bl[j].y);
        }
    }
}

// bias + relu + hi/lo split: D[2*NKT][4] -> A[NKT][4]
template <int NKT>
__device__ __forceinline__ void epi_relu_split(
    const float (*D)[4], uint32_t (*Ahi)[4], uint32_t (*Alo)[4],
    const float* __restrict__ bsm, int tig)
{
#pragma unroll
    for (int kt = 0; kt < NKT; kt++) {
#pragma unroll
        for (int half = 0; half < 2; half++) {
            int nt = 2 * kt + half;
            float b0 = bsm[nt * 8 + tig * 2];
            float b1 = bsm[nt * 8 + tig * 2 + 1];
            float v0 = fmaxf(D[nt][0] + b0, 0.f);
            float v1 = fmaxf(D[nt][1] + b1, 0.f);
            float v2 = fmaxf(D[nt][2] + b0, 0.f);
            float v3 = fmaxf(D[nt][3] + b1, 0.f);
            split2(v0, v1, Ahi[kt][half * 2 + 0], Alo[kt][half * 2 + 0]);
            split2(v2, v3, Ahi[kt][half * 2 + 1], Alo[kt][half * 2 + 1]);
        }
    }
}

__global__ __launch_bounds__(256, 1) void conv_kernel(
    const float* __restrict__ x, float* __restrict__ out)
{
    extern __shared__ __align__(16) char smem[];
    const float* bsm = (const float*)(smem + 212992);

    const int tid = threadIdx.x;
    const int w = tid >> 5, lane = tid & 31;
    const int gid = lane >> 2, tig = lane & 3;
    const int b  = blockIdx.x / 9;
    const int cs = blockIdx.x % 9;

    // stage all fragment-ordered weights (212992 B) + biases (2 KB)
    {
        const uint4* src = (const uint4*)(g_wb + (size_t)b * WS);
        uint4* dst = (uint4*)smem;
        for (int i = tid; i < 13312; i += 256) dst[i] = src[i];
        const float4* bsrc = (const float4*)(g_bias + b * 512);
        float4* bdst = (float4*)(smem + 212992);
        if (tid < 128) bdst[tid] = bsrc[tid];
    }
    __syncthreads();

    const float* xb = x + (size_t)b * FIN * HW;
    float* ob = out + (size_t)b * FOUT * HW;

    float    D[16][4];
    uint32_t Xhi[4][4], Xlo[4][4];
    uint32_t Ahi[8][4], Alo[8][4];

    for (int t = cs; t < 128; t += 9) {
        const int p0 = t * 128;
        const int px_lo = p0 + w * 16 + gid;
        const int px_hi = px_lo + 8;

        // ---- load x as A fragments (bf16 hi/lo) ----
#pragma unroll
        for (int kt = 0; kt < 4; kt++) {
            const float* xp = xb + (size_t)(kt * 16 + tig * 2) * HW;
            float e00 = xp[px_lo],          e01 = xp[HW + px_lo];
            float e10 = xp[px_hi],          e11 = xp[HW + px_hi];
            float e20 = xp[8 * HW + px_lo], e21 = xp[9 * HW + px_lo];
            float e30 = xp[8 * HW + px_hi], e31 = xp[9 * HW + px_hi];
            split2(e00, e01, Xhi[kt][0], Xlo[kt][0]);
            split2(e10, e11, Xhi[kt][1], Xlo[kt][1]);
            split2(e20, e21, Xhi[kt][2], Xlo[kt][2]);
            split2(e30, e31, Xhi[kt][3], Xlo[kt][3]);
        }

        // ---- layer in: D = Win @ x ----
        layer_mma<4, 16, true>(D, Xhi, Xlo, smem, WIN_HI * 2, (WIN_HI + 8192) * 2, lane);
        epi_relu_split<8>(D, Ahi, Alo, bsm + 0, tig);

        // ---- layer mida ----
        layer_mma<8, 16, true>(D, Ahi, Alo, smem, WMIDA_HI * 2, (WMIDA_HI + 16384) * 2, lane);
        epi_relu_split<8>(D, Ahi, Alo, bsm + 128, tig);

        // ---- layer midb ----
        layer_mma<8, 16, true>(D, Ahi, Alo, smem, WMIDB_HI * 2, (WMIDB_HI + 16384) * 2, lane);
        epi_relu_split<8>(D, Ahi, Alo, bsm + 256, tig);

        // ---- out: D = Wout @ h + Wshort @ x ----
        layer_mma<8, 8, true >(D, Ahi, Alo, smem, WOUT_HI * 2, (WOUT_HI + 8192) * 2, lane);
        layer_mma<4, 8, false>(D, Xhi, Xlo, smem, WSH_HI * 2,  (WSH_HI + 4096) * 2, lane);

        // ---- final epilogue: + b_out + b_short -> gmem ----
#pragma unroll
        for (int nt = 0; nt < 8; nt++) {
            int ch = nt * 8 + tig * 2;
            float b0 = bsm[384 + ch]     + bsm[448 + ch];
            float b1 = bsm[384 + ch + 1] + bsm[448 + ch + 1];
            float* op = ob + (size_t)ch * HW;
            op[px_lo]      = D[nt][0] + b0;
            op[HW + px_lo] = D[nt][1] + b1;
            op[px_hi]      = D[nt][2] + b0;
            op[HW + px_hi] = D[nt][3] + b1;
        }
    }
}

// ============================================================
extern "C" void kernel_launch(void* const* d_in, const int* in_sizes, int n_in,
                              void* d_out, int out_size)
{
    (void)in_sizes; (void)n_in; (void)out_size;
    const float* x    = (const float*)d_in[0];
    const float* lat  = (const float*)d_in[1];
    const float* W    = (const float*)d_in[2];
    const float* bias = (const float*)d_in[3];
    float* out = (float*)d_out;

    hyper_kernel<<<KTOT / 256, 256>>>(lat, W, bias);

    cudaFuncSetAttribute(conv_kernel,
                         cudaFuncAttributeMaxDynamicSharedMemorySize, 215040);
    conv_kernel<<<16 * 9, 256, 215040>>>(x, out);
}

// round 5
// speedup vs baseline: 1.3305x; 1.3305x over previous
#include <cuda_runtime.h>
#include <cuda_fp16.h>
#include <cstdint>

#define FIN   64
#define FOUT  64
#define FH    128
#define LATD  512
#define NB    16
#define HW    16384
#define KTOT  53760
#define WS    106496   // fp16 elements of packed weights per sample

// per-sample fp16 element offsets of fragment-ordered weight buffers
#define WIN_HI   0        // O=128 I=64  (8192 ele), lo at +8192
#define WMIDA_HI 16384    // O=128 I=128 (16384),   lo at +16384
#define WMIDB_HI 49152
#define WOUT_HI  81920    // O=64 I=128  (8192),    lo at +8192
#define WSH_HI   98304    // O=64 I=64   (4096),    lo at +4096

__device__ __align__(16) __half g_wh[NB * WS];
__device__ __align__(16) float g_bias[NB * 512];

// ---------------- helpers ----------------
__device__ __forceinline__ uint32_t pack_f16x2(float f0, float f1) {
    // low half = f0, high half = f1
    uint32_t r;
    asm("cvt.rn.f16x2.f32 %0, %1, %2;" : "=r"(r) : "f"(f1), "f"(f0));
    return r;
}

__device__ __forceinline__ void mma16816(float d[4],
    const uint32_t a[4], uint32_t b0, uint32_t b1)
{
    asm volatile(
        "mma.sync.aligned.m16n8k16.row.col.f32.f16.f16.f32 "
        "{%0,%1,%2,%3}, {%4,%5,%6,%7}, {%8,%9}, {%0,%1,%2,%3};"
        : "+f"(d[0]), "+f"(d[1]), "+f"(d[2]), "+f"(d[3])
        : "r"(a[0]), "r"(a[1]), "r"(a[2]), "r"(a[3]), "r"(b0), "r"(b1));
}

// ============================================================
// Kernel A: hypernetwork GEMM (scalar FFMA, 16 sample accs)
// + fp16 hi/lo pack into mma.sync B-fragment order.
// 420 CTAs x 128 threads for wave balance (2.84 waves).
// ============================================================
__global__ __launch_bounds__(128) void hyper_kernel(
    const float* __restrict__ lat,
    const float* __restrict__ Wm,
    const float* __restrict__ bias)
{
    __shared__ float slat[NB][LATD];   // 32 KB
    for (int i = threadIdx.x; i < NB * LATD; i += 128)
        slat[i >> 9][i & 511] = lat[i];
    __syncthreads();

    int k = blockIdx.x * 128 + threadIdx.x;   // 420*128 == 53760 exact

    float acc[NB];
#pragma unroll
    for (int s = 0; s < NB; s++) acc[s] = 0.f;

    const float4* wr = (const float4*)(Wm + (size_t)k * LATD);
#pragma unroll 4
    for (int l4 = 0; l4 < LATD / 4; l4++) {
        float4 w = wr[l4];
        int l = l4 * 4;
#pragma unroll
        for (int s = 0; s < NB; s++) {
            acc[s] = fmaf(w.x, slat[s][l + 0], acc[s]);
            acc[s] = fmaf(w.y, slat[s][l + 1], acc[s]);
            acc[s] = fmaf(w.z, slat[s][l + 2], acc[s]);
            acc[s] = fmaf(w.w, slat[s][l + 3], acc[s]);
        }
    }

    const float RS128 = 0.08838834764831845f;  // 1/sqrt(128)
    const float RS64  = 0.125f;                // 1/sqrt(64)
    float bk = bias[k];

    // map k -> (layer, o, i) -> fragment element index
    bool isBias = false;
    float scale = 1.f;
    int o = 0, i = 0, I = 0, baseHi = 0, loDelta = 0;
    if (k < 8192) {
        o = k >> 6; i = k & 63; I = 64;
        baseHi = WIN_HI; loDelta = 8192; scale = RS128;
    } else if (k < 24576) {
        int idx = k - 8192; o = idx >> 7; i = idx & 127; I = 128;
        baseHi = WMIDA_HI; loDelta = 16384; scale = RS128;
    } else if (k < 40960) {
        int idx = k - 24576; o = idx >> 7; i = idx & 127; I = 128;
        baseHi = WMIDB_HI; loDelta = 16384; scale = RS128;
    } else if (k < 49152) {
        int idx = k - 40960; o = idx >> 7; i = idx & 127; I = 128;
        baseHi = WOUT_HI; loDelta = 8192; scale = RS64;
    } else if (k < 53248) {
        int idx = k - 49152; o = idx >> 6; i = idx & 63; I = 64;
        baseHi = WSH_HI; loDelta = 4096; scale = RS64;
    } else {
        isBias = true;
    }

    int fel = 0;
    if (!isBias) {
        int KT = I / 16;
        int nt = o >> 3, kt = i >> 4;
        int tl = (o & 7) * 4 + ((i & 7) >> 1);          // lane
        int el = (((i >> 3) & 1) << 1) | (i & 1);       // elem within 4-group
        fel = baseHi + ((nt * KT + kt) * 32 + tl) * 4 + el;
    }

#pragma unroll
    for (int s = 0; s < NB; s++) {
        if (isBias) {
            g_bias[s * 512 + (k - 53248)] = acc[s] + bk;
        } else {
            float v = (acc[s] + bk) * scale;
            __half h = __float2half_rn(v);
            __half l = __float2half_rn(v - __half2float(h));
            g_wh[(size_t)s * WS + fel]           = h;
            g_wh[(size_t)s * WS + fel + loDelta] = l;
        }
    }
}

// ============================================================
// Kernel B: mma.sync fused block; activations register-resident fp16,
// weights fp16 hi/lo (2-term split: D = A*Bhi + A*Blo).
// ============================================================
template <int KT, int NT, bool ZERO>
__device__ __forceinline__ void layer_mma(
    float (*D)[4], const uint32_t (*A)[4],
    const char* __restrict__ sm, int hiOffB, int loOffB, int lane)
{
    if (ZERO) {
#pragma unroll
        for (int nt = 0; nt < NT; nt++) {
            D[nt][0] = 0.f; D[nt][1] = 0.f; D[nt][2] = 0.f; D[nt][3] = 0.f;
        }
    }
#pragma unroll
    for (int kt = 0; kt < KT; kt++) {
#pragma unroll
        for (int nc = 0; nc < NT; nc += 8) {
            uint2 bh[8], bl[8];
#pragma unroll
            for (int j = 0; j < 8; j++) {
                int fo = (((nc + j) * KT + kt) * 32 + lane) * 8;
                bh[j] = *(const uint2*)(sm + hiOffB + fo);
                bl[j] = *(const uint2*)(sm + loOffB + fo);
            }
#pragma unroll
            for (int j = 0; j < 8; j++) mma16816(D[nc + j], A[kt], bh[j].x, bh[j].y);
#pragma unroll
            for (int j = 0; j < 8; j++) mma16816(D[nc + j], A[kt], bl[j].x, bl[j].y);
        }
    }
}

// bias + relu + fp16 pack: D[2*NKT][4] -> A[NKT][4]
template <int NKT>
__device__ __forceinline__ void epi_relu_pack(
    const float (*D)[4], uint32_t (*A)[4],
    const float* __restrict__ bsm, int tig)
{
#pragma unroll
    for (int kt = 0; kt < NKT; kt++) {
#pragma unroll
        for (int half = 0; half < 2; half++) {
            int nt = 2 * kt + half;
            float b0 = bsm[nt * 8 + tig * 2];
            float b1 = bsm[nt * 8 + tig * 2 + 1];
            float v0 = fmaxf(D[nt][0] + b0, 0.f);
            float v1 = fmaxf(D[nt][1] + b1, 0.f);
            float v2 = fmaxf(D[nt][2] + b0, 0.f);
            float v3 = fmaxf(D[nt][3] + b1, 0.f);
            A[kt][half * 2 + 0] = pack_f16x2(v0, v1);
            A[kt][half * 2 + 1] = pack_f16x2(v2, v3);
        }
    }
}

__global__ __launch_bounds__(256, 1) void conv_kernel(
    const float* __restrict__ x, float* __restrict__ out)
{
    extern __shared__ __align__(16) char smem[];
    const float* bsm = (const float*)(smem + 212992);

    const int tid = threadIdx.x;
    const int w = tid >> 5, lane = tid & 31;
    const int gid = lane >> 2, tig = lane & 3;
    const int b  = blockIdx.x / 9;
    const int cs = blockIdx.x % 9;

    // stage all fragment-ordered weights (212992 B) + biases (2 KB)
    {
        const uint4* src = (const uint4*)(g_wh + (size_t)b * WS);
        uint4* dst = (uint4*)smem;
        for (int i = tid; i < 13312; i += 256) dst[i] = src[i];
        const float4* bsrc = (const float4*)(g_bias + b * 512);
        float4* bdst = (float4*)(smem + 212992);
        if (tid < 128) bdst[tid] = bsrc[tid];
    }
    __syncthreads();

    const float* xb = x + (size_t)b * FIN * HW;
    float* ob = out + (size_t)b * FOUT * HW;

    float    D[16][4];
    uint32_t X[4][4];
    uint32_t A[8][4];

    for (int t = cs; t < 128; t += 9) {
        const int p0 = t * 128;
        const int px_lo = p0 + w * 16 + gid;
        const int px_hi = px_lo + 8;

        // ---- load x as fp16 A fragments ----
#pragma unroll
        for (int kt = 0; kt < 4; kt++) {
            const float* xp = xb + (size_t)(kt * 16 + tig * 2) * HW;
            float e00 = xp[px_lo],          e01 = xp[HW + px_lo];
            float e10 = xp[px_hi],          e11 = xp[HW + px_hi];
            float e20 = xp[8 * HW + px_lo], e21 = xp[9 * HW + px_lo];
            float e30 = xp[8 * HW + px_hi], e31 = xp[9 * HW + px_hi];
            X[kt][0] = pack_f16x2(e00, e01);
            X[kt][1] = pack_f16x2(e10, e11);
            X[kt][2] = pack_f16x2(e20, e21);
            X[kt][3] = pack_f16x2(e30, e31);
        }

        // ---- layer in: D = Win @ x ----
        layer_mma<4, 16, true>(D, X, smem, WIN_HI * 2, (WIN_HI + 8192) * 2, lane);
        epi_relu_pack<8>(D, A, bsm + 0, tig);

        // ---- layer mida ----
        layer_mma<8, 16, true>(D, A, smem, WMIDA_HI * 2, (WMIDA_HI + 16384) * 2, lane);
        epi_relu_pack<8>(D, A, bsm + 128, tig);

        // ---- layer midb ----
        layer_mma<8, 16, true>(D, A, smem, WMIDB_HI * 2, (WMIDB_HI + 16384) * 2, lane);
        epi_relu_pack<8>(D, A, bsm + 256, tig);

        // ---- out: D = Wout @ h + Wshort @ x ----
        layer_mma<8, 8, true >(D, A, smem, WOUT_HI * 2, (WOUT_HI + 8192) * 2, lane);
        layer_mma<4, 8, false>(D, X, smem, WSH_HI * 2,  (WSH_HI + 4096) * 2, lane);

        // ---- final epilogue: + b_out + b_short -> gmem ----
#pragma unroll
        for (int nt = 0; nt < 8; nt++) {
            int ch = nt * 8 + tig * 2;
            float b0 = bsm[384 + ch]     + bsm[448 + ch];
            float b1 = bsm[384 + ch + 1] + bsm[448 + ch + 1];
            float* op = ob + (size_t)ch * HW;
            op[px_lo]      = D[nt][0] + b0;
            op[HW + px_lo] = D[nt][1] + b1;
            op[px_hi]      = D[nt][2] + b0;
            op[HW + px_hi] = D[nt][3] + b1;
        }
    }
}

// ============================================================
extern "C" void kernel_launch(void* const* d_in, const int* in_sizes, int n_in,
                              void* d_out, int out_size)
{
    (void)in_sizes; (void)n_in; (void)out_size;
    const float* x    = (const float*)d_in[0];
    const float* lat  = (const float*)d_in[1];
    const float* W    = (const float*)d_in[2];
    const float* bias = (const float*)d_in[3];
    float* out = (float*)d_out;

    hyper_kernel<<<KTOT / 128, 128>>>(lat, W, bias);

    cudaFuncSetAttribute(conv_kernel,
                         cudaFuncAttributeMaxDynamicSharedMemorySize, 215040);
    conv_kernel<<<16 * 9, 256, 215040>>>(x, out);
}